// round 2
// baseline (speedup 1.0000x reference)
#include <cuda_runtime.h>
#include <cuda_bf16.h>
#include <math.h>

#define N_NODES 100000
#define N_EDGES 1600000
#define F_IN 512
#define HID 156
#define N_CLS 7

// ---------------- static scratch (no allocations allowed) ----------------
__device__ float g_hs[(size_t)N_NODES * HID];   // dis[i] * (x@W1)[i]
__device__ float g_a1[(size_t)N_NODES * HID];   // relu(agg1 + b1)
__device__ float g_gs[(size_t)N_NODES * 8];     // dis[i] * (a1@W2)[i], padded to 8
__device__ int   g_deg[N_NODES];
__device__ int   g_cursor[N_NODES];
__device__ int   g_rowptr[N_NODES + 1];
__device__ int   g_col[N_EDGES];
__device__ float g_dis[N_NODES];

// ---------------- graph build ----------------
__global__ void zero_kernel() {
    int i = blockIdx.x * blockDim.x + threadIdx.x;
    if (i < N_NODES) { g_deg[i] = 0; g_cursor[i] = 0; }
}

__global__ void count_kernel(const int* __restrict__ edge) {
    int e = blockIdx.x * blockDim.x + threadIdx.x;
    if (e < N_EDGES) {
        int d = edge[N_EDGES + e];   // dst row
        atomicAdd(&g_deg[d], 1);
    }
}

// single-block exclusive scan over g_deg -> g_rowptr, plus dis = rsqrt(deg+1)
__global__ void scan_kernel() {
    __shared__ int warp_sums[32];
    __shared__ int s_carry;
    int tid = threadIdx.x, lane = tid & 31, wid = tid >> 5;
    if (tid == 0) s_carry = 0;
    __syncthreads();
    for (int base = 0; base < N_NODES; base += 1024) {
        int i = base + tid;
        int v = (i < N_NODES) ? g_deg[i] : 0;
        int x = v;
        #pragma unroll
        for (int o = 1; o < 32; o <<= 1) {
            int t = __shfl_up_sync(0xffffffffu, x, o);
            if (lane >= o) x += t;
        }
        if (lane == 31) warp_sums[wid] = x;
        __syncthreads();
        if (wid == 0) {
            int s = warp_sums[lane];
            #pragma unroll
            for (int o = 1; o < 32; o <<= 1) {
                int t = __shfl_up_sync(0xffffffffu, s, o);
                if (lane >= o) s += t;
            }
            warp_sums[lane] = s;
        }
        __syncthreads();
        int off = s_carry + (wid > 0 ? warp_sums[wid - 1] : 0);
        if (i < N_NODES) {
            g_rowptr[i] = off + x - v;          // exclusive
            g_dis[i] = rsqrtf((float)(v + 1));  // +1 self loop
        }
        int total = warp_sums[31];
        __syncthreads();
        if (tid == 0) s_carry += total;
        __syncthreads();   // total consumed + s_carry visible before next iter writes
    }
    if (tid == 0) g_rowptr[N_NODES] = s_carry;
}

__global__ void scatter_kernel(const int* __restrict__ edge) {
    int e = blockIdx.x * blockDim.x + threadIdx.x;
    if (e < N_EDGES) {
        int s = edge[e];
        int d = edge[N_EDGES + e];
        int p = g_rowptr[d] + atomicAdd(&g_cursor[d], 1);
        g_col[p] = s;
    }
}

// ---------------- GEMM1: hs = dis[row] * (x @ W1) ----------------
// BM=64, BN=160 (156 padded), BK=16, 256 threads (16x16, 4x10 micro-tile)
#define BM 64
#define BN 160
#define BK 16
__global__ __launch_bounds__(256) void gemm1_kernel(const float* __restrict__ X,
                                                    const float* __restrict__ W) {
    __shared__ float As[BK][BM + 4];
    __shared__ float Bs[BK][BN];
    int block_m = blockIdx.x * BM;
    int tid = threadIdx.x;
    int tx = tid & 15;   // n group: 10 cols
    int ty = tid >> 4;   // m group: 4 rows
    float acc[4][10];
    #pragma unroll
    for (int r = 0; r < 4; r++)
        #pragma unroll
        for (int c = 0; c < 10; c++) acc[r][c] = 0.f;

    int a_row = tid >> 2;          // 0..63
    int a_kq  = (tid & 3) * 4;     // float4 along k

    for (int k0 = 0; k0 < F_IN; k0 += BK) {
        // A tile (64 x 16), stored k-major
        int gm = block_m + a_row;
        float4 av = make_float4(0.f, 0.f, 0.f, 0.f);
        if (gm < N_NODES)
            av = *(const float4*)(X + (size_t)gm * F_IN + k0 + a_kq);
        As[a_kq + 0][a_row] = av.x;
        As[a_kq + 1][a_row] = av.y;
        As[a_kq + 2][a_row] = av.z;
        As[a_kq + 3][a_row] = av.w;
        // B tile (16 x 160), 640 float4 slots
        #pragma unroll
        for (int l = 0; l < 3; l++) {
            int idx = tid + l * 256;
            if (idx < 640) {
                int bk = idx / 40;
                int bf = (idx % 40) * 4;
                float4 bv = make_float4(0.f, 0.f, 0.f, 0.f);
                if (bf < HID)
                    bv = *(const float4*)(W + (size_t)(k0 + bk) * HID + bf);
                Bs[bk][bf + 0] = bv.x;
                Bs[bk][bf + 1] = bv.y;
                Bs[bk][bf + 2] = bv.z;
                Bs[bk][bf + 3] = bv.w;
            }
        }
        __syncthreads();
        #pragma unroll
        for (int k = 0; k < BK; k++) {
            float a[4], b[10];
            #pragma unroll
            for (int r = 0; r < 4; r++) a[r] = As[k][ty * 4 + r];
            #pragma unroll
            for (int c = 0; c < 10; c++) b[c] = Bs[k][tx * 10 + c];
            #pragma unroll
            for (int r = 0; r < 4; r++)
                #pragma unroll
                for (int c = 0; c < 10; c++) acc[r][c] += a[r] * b[c];
        }
        __syncthreads();
    }
    #pragma unroll
    for (int r = 0; r < 4; r++) {
        int m = block_m + ty * 4 + r;
        if (m < N_NODES) {
            float d = g_dis[m];
            float* out = g_hs + (size_t)m * HID;
            #pragma unroll
            for (int c = 0; c < 10; c++) {
                int n = tx * 10 + c;
                if (n < HID) out[n] = d * acc[r][c];
            }
        }
    }
}

// ---------------- agg1: a1 = relu(b1 + dis[i]*(sum_{j in N(i)} hs[j] + hs[i])) ----
__global__ __launch_bounds__(256) void agg1_kernel(const float* __restrict__ b1) {
    int warp = (blockIdx.x * blockDim.x + threadIdx.x) >> 5;
    int lane = threadIdx.x & 31;
    if (warp >= N_NODES) return;
    int i = warp;
    const float* self = g_hs + (size_t)i * HID;
    float a0 = self[lane];
    float a1v = self[lane + 32];
    float a2 = self[lane + 64];
    float a3 = self[lane + 96];
    float a4 = (lane < HID - 128) ? self[lane + 128] : 0.f;
    int s = g_rowptr[i], e = g_rowptr[i + 1];
    int p = s;
    for (; p + 1 < e; p += 2) {
        int j0 = g_col[p];
        int j1 = g_col[p + 1];
        const float* r0 = g_hs + (size_t)j0 * HID;
        const float* r1 = g_hs + (size_t)j1 * HID;
        a0 += r0[lane];      a0 += r1[lane];
        a1v += r0[lane + 32]; a1v += r1[lane + 32];
        a2 += r0[lane + 64]; a2 += r1[lane + 64];
        a3 += r0[lane + 96]; a3 += r1[lane + 96];
        if (lane < HID - 128) { a4 += r0[lane + 128]; a4 += r1[lane + 128]; }
    }
    if (p < e) {
        int j0 = g_col[p];
        const float* r0 = g_hs + (size_t)j0 * HID;
        a0 += r0[lane]; a1v += r0[lane + 32]; a2 += r0[lane + 64]; a3 += r0[lane + 96];
        if (lane < HID - 128) a4 += r0[lane + 128];
    }
    float d = g_dis[i];
    float* out = g_a1 + (size_t)i * HID;
    out[lane]       = fmaxf(d * a0 + b1[lane], 0.f);
    out[lane + 32]  = fmaxf(d * a1v + b1[lane + 32], 0.f);
    out[lane + 64]  = fmaxf(d * a2 + b1[lane + 64], 0.f);
    out[lane + 96]  = fmaxf(d * a3 + b1[lane + 96], 0.f);
    if (lane < HID - 128)
        out[lane + 128] = fmaxf(d * a4 + b1[lane + 128], 0.f);
}

// ---------------- gemm2 + scale: gs[i] = dis[i] * (a1[i] @ W2), pad col 7 = 0 ----
__global__ __launch_bounds__(256) void gemm2_kernel(const float* __restrict__ W2) {
    __shared__ float sW2[HID * N_CLS];
    for (int t = threadIdx.x; t < HID * N_CLS; t += blockDim.x) sW2[t] = W2[t];
    __syncthreads();
    int warp = (blockIdx.x * blockDim.x + threadIdx.x) >> 5;
    int lane = threadIdx.x & 31;
    if (warp >= N_NODES) return;
    int i = warp;
    const float* arow = g_a1 + (size_t)i * HID;
    float p[N_CLS];
    #pragma unroll
    for (int c = 0; c < N_CLS; c++) p[c] = 0.f;
    #pragma unroll
    for (int k = 0; k < 5; k++) {
        int f = lane + 32 * k;
        if (f < HID) {
            float a = arow[f];
            #pragma unroll
            for (int c = 0; c < N_CLS; c++) p[c] += a * sW2[f * N_CLS + c];
        }
    }
    #pragma unroll
    for (int c = 0; c < N_CLS; c++) {
        #pragma unroll
        for (int o = 16; o > 0; o >>= 1)
            p[c] += __shfl_xor_sync(0xffffffffu, p[c], o);
    }
    if (lane == 0) {
        float d = g_dis[i];
        float* out = g_gs + (size_t)i * 8;
        #pragma unroll
        for (int c = 0; c < N_CLS; c++) out[c] = d * p[c];
        out[7] = 0.f;
    }
}

// ---------------- agg2 + bias + log_softmax -> d_out ----------------
__global__ __launch_bounds__(256) void agg2_kernel(const float* __restrict__ b2,
                                                   float* __restrict__ out) {
    int t = blockIdx.x * blockDim.x + threadIdx.x;
    int i = t >> 3;
    int sl = t & 7;
    if (i >= N_NODES) return;
    float acc[8];
    #pragma unroll
    for (int c = 0; c < 8; c++) acc[c] = 0.f;
    int s = g_rowptr[i], e = g_rowptr[i + 1];
    for (int p = s + sl; p < e; p += 8) {
        int j = g_col[p];
        const float4* g = (const float4*)(g_gs + (size_t)j * 8);
        float4 u = g[0], v = g[1];
        acc[0] += u.x; acc[1] += u.y; acc[2] += u.z; acc[3] += u.w;
        acc[4] += v.x; acc[5] += v.y; acc[6] += v.z;
    }
    if (sl == 0) {
        const float4* g = (const float4*)(g_gs + (size_t)i * 8);
        float4 u = g[0], v = g[1];
        acc[0] += u.x; acc[1] += u.y; acc[2] += u.z; acc[3] += u.w;
        acc[4] += v.x; acc[5] += v.y; acc[6] += v.z;
    }
    #pragma unroll
    for (int off = 4; off > 0; off >>= 1) {
        #pragma unroll
        for (int c = 0; c < N_CLS; c++)
            acc[c] += __shfl_down_sync(0xffffffffu, acc[c], off);
    }
    if (sl == 0) {
        float d = g_dis[i];
        float v[N_CLS];
        float m = -1e30f;
        #pragma unroll
        for (int c = 0; c < N_CLS; c++) {
            v[c] = d * acc[c] + b2[c];
            m = fmaxf(m, v[c]);
        }
        float ssum = 0.f;
        #pragma unroll
        for (int c = 0; c < N_CLS; c++) ssum += __expf(v[c] - m);
        float lse = m + logf(ssum);
        float* o = out + (size_t)i * N_CLS;
        #pragma unroll
        for (int c = 0; c < N_CLS; c++) o[c] = v[c] - lse;
    }
}

// ---------------- launch ----------------
extern "C" void kernel_launch(void* const* d_in, const int* in_sizes, int n_in,
                              void* d_out, int out_size) {
    const float* x    = (const float*)d_in[0];
    const int*   edge = (const int*)d_in[1];
    const float* W1   = (const float*)d_in[2];
    const float* b1   = (const float*)d_in[3];
    const float* W2   = (const float*)d_in[4];
    const float* b2   = (const float*)d_in[5];
    float* out = (float*)d_out;

    zero_kernel<<<(N_NODES + 255) / 256, 256>>>();
    count_kernel<<<(N_EDGES + 255) / 256, 256>>>(edge);
    scan_kernel<<<1, 1024>>>();
    scatter_kernel<<<(N_EDGES + 255) / 256, 256>>>(edge);
    gemm1_kernel<<<(N_NODES + BM - 1) / BM, 256>>>(x, W1);
    agg1_kernel<<<(N_NODES * 32 + 255) / 256, 256>>>(b1);
    gemm2_kernel<<<(N_NODES * 32 + 255) / 256, 256>>>(W2);
    agg2_kernel<<<(N_NODES * 8 + 255) / 256, 256>>>(b2, out);
}

// round 4
// speedup vs baseline: 1.4836x; 1.4836x over previous
#include <cuda_runtime.h>
#include <cuda_bf16.h>
#include <math.h>
#include <stdint.h>

#define N_NODES 100000
#define N_EDGES 1600000
#define F_IN 512
#define HID 156
#define N_CLS 7

// ---------------- static scratch (no allocations allowed) ----------------
__device__ float g_hs[(size_t)N_NODES * HID];   // dis[i] * (x@W1)[i]
__device__ float g_a1[(size_t)N_NODES * HID];   // relu(agg1 + b1)
__device__ float g_gs[(size_t)N_NODES * 8];     // dis[i] * (a1@W2)[i], padded to 8
__device__ int   g_deg[N_NODES];
__device__ int   g_cursor[N_NODES];
__device__ int   g_rowptr[N_NODES + 1];
__device__ int   g_col[N_EDGES];
__device__ float g_dis[N_NODES];

// ---------------- helpers ----------------
__device__ __forceinline__ uint32_t smem_u32(const void* p) {
    uint32_t a;
    asm("{ .reg .u64 t; cvta.to.shared.u64 t, %1; cvt.u32.u64 %0, t; }" : "=r"(a) : "l"(p));
    return a;
}
__device__ __forceinline__ void ldm4(uint32_t* r, uint32_t addr) {
    asm volatile("ldmatrix.sync.aligned.m8n8.x4.shared.b16 {%0,%1,%2,%3}, [%4];"
                 : "=r"(r[0]), "=r"(r[1]), "=r"(r[2]), "=r"(r[3]) : "r"(addr));
}
__device__ __forceinline__ void mma16816(float* d, const uint32_t* a,
                                         uint32_t b0, uint32_t b1) {
    asm volatile(
        "mma.sync.aligned.m16n8k16.row.col.f32.bf16.bf16.f32 "
        "{%0,%1,%2,%3}, {%4,%5,%6,%7}, {%8,%9}, {%0,%1,%2,%3};"
        : "+f"(d[0]), "+f"(d[1]), "+f"(d[2]), "+f"(d[3])
        : "r"(a[0]), "r"(a[1]), "r"(a[2]), "r"(a[3]), "r"(b0), "r"(b1));
}

// ---------------- graph build ----------------
__global__ void zero_kernel() {
    int i = blockIdx.x * blockDim.x + threadIdx.x;
    if (i < N_NODES) { g_deg[i] = 0; g_cursor[i] = 0; }
}

__global__ void count_kernel(const int* __restrict__ edge) {
    int e = blockIdx.x * blockDim.x + threadIdx.x;
    if (e < N_EDGES) {
        int d = edge[N_EDGES + e];
        atomicAdd(&g_deg[d], 1);
    }
}

__global__ void scan_kernel() {
    __shared__ int warp_sums[32];
    __shared__ int s_carry;
    int tid = threadIdx.x, lane = tid & 31, wid = tid >> 5;
    if (tid == 0) s_carry = 0;
    __syncthreads();
    for (int base = 0; base < N_NODES; base += 1024) {
        int i = base + tid;
        int v = (i < N_NODES) ? g_deg[i] : 0;
        int x = v;
        #pragma unroll
        for (int o = 1; o < 32; o <<= 1) {
            int t = __shfl_up_sync(0xffffffffu, x, o);
            if (lane >= o) x += t;
        }
        if (lane == 31) warp_sums[wid] = x;
        __syncthreads();
        if (wid == 0) {
            int s = warp_sums[lane];
            #pragma unroll
            for (int o = 1; o < 32; o <<= 1) {
                int t = __shfl_up_sync(0xffffffffu, s, o);
                if (lane >= o) s += t;
            }
            warp_sums[lane] = s;
        }
        __syncthreads();
        int off = s_carry + (wid > 0 ? warp_sums[wid - 1] : 0);
        if (i < N_NODES) {
            g_rowptr[i] = off + x - v;
            g_dis[i] = rsqrtf((float)(v + 1));
        }
        int total = warp_sums[31];
        __syncthreads();
        if (tid == 0) s_carry += total;
        __syncthreads();
    }
    if (tid == 0) g_rowptr[N_NODES] = s_carry;
}

__global__ void scatter_kernel(const int* __restrict__ edge) {
    int e = blockIdx.x * blockDim.x + threadIdx.x;
    if (e < N_EDGES) {
        int s = edge[e];
        int d = edge[N_EDGES + e];
        int p = g_rowptr[d] + atomicAdd(&g_cursor[d], 1);
        g_col[p] = s;
    }
}

// ---------------- GEMM1 (mma.sync bf16 3-pass split): hs = dis[m]*(x@W1) ----------------
// Block tile M=64 x N=160 (156 padded). 8 warps: 4 (M) x 2 (N-80). K chunks of 16.
// SMEM rows padded to 24 halves (48B, 16B-aligned) -> conflict-free ldmatrix.
#define A_STRIDE 24
#define B_STRIDE 24
#define G1_CHUNKS (F_IN / 16)

__global__ __launch_bounds__(256) void gemm1_mma_kernel(const float* __restrict__ X,
                                                        const float* __restrict__ W) {
    __shared__ __align__(16) __nv_bfloat16 sAhi[64 * A_STRIDE];
    __shared__ __align__(16) __nv_bfloat16 sAlo[64 * A_STRIDE];
    __shared__ __align__(16) __nv_bfloat16 sBhi[160 * B_STRIDE];
    __shared__ __align__(16) __nv_bfloat16 sBlo[160 * B_STRIDE];

    int tid = threadIdx.x;
    int wid = tid >> 5;
    int lane = tid & 31;
    int warp_m = wid >> 1;     // 0..3
    int warp_n = wid & 1;      // 0..1
    int block_m = blockIdx.x * 64;

    // zero B buffers once (covers padded rows 156..159 and pad cols)
    for (int i = tid; i < 160 * B_STRIDE; i += 256) { sBhi[i] = __nv_bfloat16(0.f); sBlo[i] = __nv_bfloat16(0.f); }

    // ldmatrix source addresses
    uint32_t aHiAddr = smem_u32(sAhi) + (uint32_t)((warp_m * 16 + (lane & 15)) * A_STRIDE * 2 + (lane >> 4) * 16);
    uint32_t aLoAddr = smem_u32(sAlo) + (uint32_t)((warp_m * 16 + (lane & 15)) * A_STRIDE * 2 + (lane >> 4) * 16);
    int b_row_off = ((lane >> 4) & 1) * 8 + (lane & 7);
    int b_khalf   = ((lane >> 3) & 1) * 16;     // bytes
    uint32_t bHiBase = smem_u32(sBhi) + (uint32_t)((warp_n * 80 + b_row_off) * B_STRIDE * 2 + b_khalf);
    uint32_t bLoBase = smem_u32(sBlo) + (uint32_t)((warp_n * 80 + b_row_off) * B_STRIDE * 2 + b_khalf);

    float acc[10][4];
    #pragma unroll
    for (int f = 0; f < 10; f++)
        #pragma unroll
        for (int c = 0; c < 4; c++) acc[f][c] = 0.f;

    // A prefetch: row = tid>>2 (0..63), grp = tid&3 (float4 along k)
    int a_row = tid >> 2;
    int a_grp = tid & 3;
    int a_m = block_m + a_row;
    bool a_valid = a_m < N_NODES;
    const float4* a_src = (const float4*)(X + (size_t)a_m * F_IN) + a_grp;

    float4 aN = make_float4(0.f, 0.f, 0.f, 0.f);
    if (a_valid) aN = a_src[0];
    float bN[10];
    #pragma unroll
    for (int i = 0; i < 10; i++) {
        int idx = tid + i * 256;
        int kk = idx / 160, n = idx - kk * 160;
        bN[i] = (idx < 2560 && n < HID) ? W[(size_t)kk * HID + n] : 0.f;
    }

    for (int step = 0; step < G1_CHUNKS; step++) {
        // ---- convert + store current chunk to smem
        {
            __nv_bfloat16 h0 = __float2bfloat16(aN.x);
            __nv_bfloat16 h1 = __float2bfloat16(aN.y);
            __nv_bfloat16 h2 = __float2bfloat16(aN.z);
            __nv_bfloat16 h3 = __float2bfloat16(aN.w);
            __nv_bfloat16 l0 = __float2bfloat16(aN.x - __bfloat162float(h0));
            __nv_bfloat16 l1 = __float2bfloat16(aN.y - __bfloat162float(h1));
            __nv_bfloat16 l2 = __float2bfloat16(aN.z - __bfloat162float(h2));
            __nv_bfloat16 l3 = __float2bfloat16(aN.w - __bfloat162float(h3));
            int o = a_row * A_STRIDE + a_grp * 4;
            *(__nv_bfloat162*)(sAhi + o)     = __nv_bfloat162(h0, h1);
            *(__nv_bfloat162*)(sAhi + o + 2) = __nv_bfloat162(h2, h3);
            *(__nv_bfloat162*)(sAlo + o)     = __nv_bfloat162(l0, l1);
            *(__nv_bfloat162*)(sAlo + o + 2) = __nv_bfloat162(l2, l3);
        }
        #pragma unroll
        for (int i = 0; i < 10; i++) {
            int idx = tid + i * 256;
            if (idx < 2560) {
                int kk = idx / 160, n = idx - kk * 160;
                if (n < HID) {
                    __nv_bfloat16 h = __float2bfloat16(bN[i]);
                    __nv_bfloat16 l = __float2bfloat16(bN[i] - __bfloat162float(h));
                    sBhi[n * B_STRIDE + kk] = h;
                    sBlo[n * B_STRIDE + kk] = l;
                }
            }
        }
        __syncthreads();

        // ---- prefetch next chunk into registers (LDG overlaps MMA below)
        if (step + 1 < G1_CHUNKS) {
            int k0 = (step + 1) * 16;
            aN = make_float4(0.f, 0.f, 0.f, 0.f);
            if (a_valid) aN = a_src[k0 >> 2];
            #pragma unroll
            for (int i = 0; i < 10; i++) {
                int idx = tid + i * 256;
                int kk = idx / 160, n = idx - kk * 160;
                bN[i] = (idx < 2560 && n < HID) ? W[(size_t)(k0 + kk) * HID + n] : 0.f;
            }
        }

        // ---- MMA on smem
        uint32_t ah[4], al[4];
        ldm4(ah, aHiAddr);
        ldm4(al, aLoAddr);
        #pragma unroll
        for (int p = 0; p < 5; p++) {
            uint32_t bh[4], bl[4];
            ldm4(bh, bHiBase + (uint32_t)(p * 16 * B_STRIDE * 2));
            ldm4(bl, bLoBase + (uint32_t)(p * 16 * B_STRIDE * 2));
            mma16816(acc[2 * p],     ah, bh[0], bh[1]);
            mma16816(acc[2 * p + 1], ah, bh[2], bh[3]);
            mma16816(acc[2 * p],     ah, bl[0], bl[1]);
            mma16816(acc[2 * p + 1], ah, bl[2], bl[3]);
            mma16816(acc[2 * p],     al, bh[0], bh[1]);
            mma16816(acc[2 * p + 1], al, bh[2], bh[3]);
        }
        __syncthreads();
    }

    // ---- epilogue: scale by dis[m], store to g_hs
    int groupID = lane >> 2;
    int tig = lane & 3;
    int m0 = block_m + warp_m * 16 + groupID;
    int m1 = m0 + 8;
    bool v0 = m0 < N_NODES, v1 = m1 < N_NODES;
    float d0 = v0 ? g_dis[m0] : 0.f;
    float d1 = v1 ? g_dis[m1] : 0.f;
    float* out0 = g_hs + (size_t)m0 * HID;
    float* out1 = g_hs + (size_t)m1 * HID;
    #pragma unroll
    for (int f = 0; f < 10; f++) {
        int col = warp_n * 80 + f * 8 + tig * 2;
        if (col + 1 < HID) {
            if (v0) *(float2*)(out0 + col) = make_float2(d0 * acc[f][0], d0 * acc[f][1]);
            if (v1) *(float2*)(out1 + col) = make_float2(d1 * acc[f][2], d1 * acc[f][3]);
        }
    }
}

// ---------------- agg1: a1 = relu(b1 + dis[i]*(sum_{j in N(i)} hs[j] + hs[i])) ----
__global__ __launch_bounds__(256) void agg1_kernel(const float* __restrict__ b1) {
    int warp = (blockIdx.x * blockDim.x + threadIdx.x) >> 5;
    int lane = threadIdx.x & 31;
    if (warp >= N_NODES) return;
    int i = warp;
    const float* self = g_hs + (size_t)i * HID;
    float a0 = self[lane];
    float a1v = self[lane + 32];
    float a2 = self[lane + 64];
    float a3 = self[lane + 96];
    float a4 = (lane < HID - 128) ? self[lane + 128] : 0.f;
    int s = g_rowptr[i], e = g_rowptr[i + 1];
    int p = s;
    for (; p + 1 < e; p += 2) {
        int j0 = g_col[p];
        int j1 = g_col[p + 1];
        const float* r0 = g_hs + (size_t)j0 * HID;
        const float* r1 = g_hs + (size_t)j1 * HID;
        a0 += r0[lane];      a0 += r1[lane];
        a1v += r0[lane + 32]; a1v += r1[lane + 32];
        a2 += r0[lane + 64]; a2 += r1[lane + 64];
        a3 += r0[lane + 96]; a3 += r1[lane + 96];
        if (lane < HID - 128) { a4 += r0[lane + 128]; a4 += r1[lane + 128]; }
    }
    if (p < e) {
        int j0 = g_col[p];
        const float* r0 = g_hs + (size_t)j0 * HID;
        a0 += r0[lane]; a1v += r0[lane + 32]; a2 += r0[lane + 64]; a3 += r0[lane + 96];
        if (lane < HID - 128) a4 += r0[lane + 128];
    }
    float d = g_dis[i];
    float* out = g_a1 + (size_t)i * HID;
    out[lane]       = fmaxf(d * a0 + b1[lane], 0.f);
    out[lane + 32]  = fmaxf(d * a1v + b1[lane + 32], 0.f);
    out[lane + 64]  = fmaxf(d * a2 + b1[lane + 64], 0.f);
    out[lane + 96]  = fmaxf(d * a3 + b1[lane + 96], 0.f);
    if (lane < HID - 128)
        out[lane + 128] = fmaxf(d * a4 + b1[lane + 128], 0.f);
}

// ---------------- gemm2 + scale: gs[i] = dis[i] * (a1[i] @ W2), pad col 7 = 0 ----
__global__ __launch_bounds__(256) void gemm2_kernel(const float* __restrict__ W2) {
    __shared__ float sW2[HID * N_CLS];
    for (int t = threadIdx.x; t < HID * N_CLS; t += blockDim.x) sW2[t] = W2[t];
    __syncthreads();
    int warp = (blockIdx.x * blockDim.x + threadIdx.x) >> 5;
    int lane = threadIdx.x & 31;
    if (warp >= N_NODES) return;
    int i = warp;
    const float* arow = g_a1 + (size_t)i * HID;
    float p[N_CLS];
    #pragma unroll
    for (int c = 0; c < N_CLS; c++) p[c] = 0.f;
    #pragma unroll
    for (int k = 0; k < 5; k++) {
        int f = lane + 32 * k;
        if (f < HID) {
            float a = arow[f];
            #pragma unroll
            for (int c = 0; c < N_CLS; c++) p[c] += a * sW2[f * N_CLS + c];
        }
    }
    #pragma unroll
    for (int c = 0; c < N_CLS; c++) {
        #pragma unroll
        for (int o = 16; o > 0; o >>= 1)
            p[c] += __shfl_xor_sync(0xffffffffu, p[c], o);
    }
    if (lane == 0) {
        float d = g_dis[i];
        float* out = g_gs + (size_t)i * 8;
        #pragma unroll
        for (int c = 0; c < N_CLS; c++) out[c] = d * p[c];
        out[7] = 0.f;
    }
}

// ---------------- agg2 + bias + log_softmax -> d_out ----------------
__global__ __launch_bounds__(256) void agg2_kernel(const float* __restrict__ b2,
                                                   float* __restrict__ out) {
    int t = blockIdx.x * blockDim.x + threadIdx.x;
    int i = t >> 3;
    int sl = t & 7;
    if (i >= N_NODES) return;
    float acc[8];
    #pragma unroll
    for (int c = 0; c < 8; c++) acc[c] = 0.f;
    int s = g_rowptr[i], e = g_rowptr[i + 1];
    for (int p = s + sl; p < e; p += 8) {
        int j = g_col[p];
        const float4* g = (const float4*)(g_gs + (size_t)j * 8);
        float4 u = g[0], v = g[1];
        acc[0] += u.x; acc[1] += u.y; acc[2] += u.z; acc[3] += u.w;
        acc[4] += v.x; acc[5] += v.y; acc[6] += v.z;
    }
    if (sl == 0) {
        const float4* g = (const float4*)(g_gs + (size_t)i * 8);
        float4 u = g[0], v = g[1];
        acc[0] += u.x; acc[1] += u.y; acc[2] += u.z; acc[3] += u.w;
        acc[4] += v.x; acc[5] += v.y; acc[6] += v.z;
    }
    #pragma unroll
    for (int off = 4; off > 0; off >>= 1) {
        #pragma unroll
        for (int c = 0; c < N_CLS; c++)
            acc[c] += __shfl_down_sync(0xffffffffu, acc[c], off);
    }
    if (sl == 0) {
        float d = g_dis[i];
        float v[N_CLS];
        float m = -1e30f;
        #pragma unroll
        for (int c = 0; c < N_CLS; c++) {
            v[c] = d * acc[c] + b2[c];
            m = fmaxf(m, v[c]);
        }
        float ssum = 0.f;
        #pragma unroll
        for (int c = 0; c < N_CLS; c++) ssum += __expf(v[c] - m);
        float lse = m + logf(ssum);
        float* o = out + (size_t)i * N_CLS;
        #pragma unroll
        for (int c = 0; c < N_CLS; c++) o[c] = v[c] - lse;
    }
}

// ---------------- launch ----------------
extern "C" void kernel_launch(void* const* d_in, const int* in_sizes, int n_in,
                              void* d_out, int out_size) {
    const float* x    = (const float*)d_in[0];
    const int*   edge = (const int*)d_in[1];
    const float* W1   = (const float*)d_in[2];
    const float* b1   = (const float*)d_in[3];
    const float* W2   = (const float*)d_in[4];
    const float* b2   = (const float*)d_in[5];
    float* out = (float*)d_out;

    zero_kernel<<<(N_NODES + 255) / 256, 256>>>();
    count_kernel<<<(N_EDGES + 255) / 256, 256>>>(edge);
    scan_kernel<<<1, 1024>>>();
    scatter_kernel<<<(N_EDGES + 255) / 256, 256>>>(edge);
    gemm1_mma_kernel<<<(N_NODES + 63) / 64, 256>>>(x, W1);
    agg1_kernel<<<(N_NODES * 32 + 255) / 256, 256>>>(b1);
    gemm2_kernel<<<(N_NODES * 32 + 255) / 256, 256>>>(W2);
    agg2_kernel<<<(N_NODES * 8 + 255) / 256, 256>>>(b2, out);
}

// round 5
// speedup vs baseline: 1.8767x; 1.2649x over previous
#include <cuda_runtime.h>
#include <cuda_bf16.h>
#include <math.h>
#include <stdint.h>

#define N_NODES 100000
#define N_EDGES 1600000
#define F_IN 512
#define HID 156
#define N_CLS 7

// ---------------- static scratch (no allocations allowed) ----------------
__device__ float g_hs[(size_t)N_NODES * HID];   // dis[i] * (x@W1)[i]
__device__ float g_a1[(size_t)N_NODES * HID];   // relu(agg1 + b1)
__device__ float g_gs[(size_t)N_NODES * 8];     // dis[i] * (a1@W2)[i], padded to 8
__device__ int   g_deg[N_NODES];
__device__ int   g_cursor[N_NODES];
__device__ int   g_rowptr[N_NODES + 1];
__device__ int   g_col[N_EDGES];
__device__ float g_dis[N_NODES];
// pre-split W1, transposed to n-major [160][512], bf16 hi/lo (rows 156..159 zero)
__device__ __nv_bfloat16 g_w1t_hi[160 * F_IN];
__device__ __nv_bfloat16 g_w1t_lo[160 * F_IN];

// ---------------- helpers ----------------
__device__ __forceinline__ uint32_t smem_u32(const void* p) {
    uint32_t a;
    asm("{ .reg .u64 t; cvta.to.shared.u64 t, %1; cvt.u32.u64 %0, t; }" : "=r"(a) : "l"(p));
    return a;
}
__device__ __forceinline__ void ldm4(uint32_t* r, uint32_t addr) {
    asm volatile("ldmatrix.sync.aligned.m8n8.x4.shared.b16 {%0,%1,%2,%3}, [%4];"
                 : "=r"(r[0]), "=r"(r[1]), "=r"(r[2]), "=r"(r[3]) : "r"(addr));
}
__device__ __forceinline__ void mma16816(float* d, const uint32_t* a,
                                         uint32_t b0, uint32_t b1) {
    asm volatile(
        "mma.sync.aligned.m16n8k16.row.col.f32.bf16.bf16.f32 "
        "{%0,%1,%2,%3}, {%4,%5,%6,%7}, {%8,%9}, {%0,%1,%2,%3};"
        : "+f"(d[0]), "+f"(d[1]), "+f"(d[2]), "+f"(d[3])
        : "r"(a[0]), "r"(a[1]), "r"(a[2]), "r"(a[3]), "r"(b0), "r"(b1));
}
__device__ __forceinline__ uint32_t pack_bf2(float a, float b) {
    __nv_bfloat162 t = __floats2bfloat162_rn(a, b);
    return *(uint32_t*)&t;
}

// ---------------- graph build ----------------
__global__ void zero_kernel() {
    int i = blockIdx.x * blockDim.x + threadIdx.x;
    if (i < N_NODES) { g_deg[i] = 0; g_cursor[i] = 0; }
}

__global__ void count_kernel(const int* __restrict__ edge) {
    int e = blockIdx.x * blockDim.x + threadIdx.x;
    if (e < N_EDGES) {
        int d = edge[N_EDGES + e];
        atomicAdd(&g_deg[d], 1);
    }
}

__global__ void scan_kernel() {
    __shared__ int warp_sums[32];
    __shared__ int s_carry;
    int tid = threadIdx.x, lane = tid & 31, wid = tid >> 5;
    if (tid == 0) s_carry = 0;
    __syncthreads();
    for (int base = 0; base < N_NODES; base += 1024) {
        int i = base + tid;
        int v = (i < N_NODES) ? g_deg[i] : 0;
        int x = v;
        #pragma unroll
        for (int o = 1; o < 32; o <<= 1) {
            int t = __shfl_up_sync(0xffffffffu, x, o);
            if (lane >= o) x += t;
        }
        if (lane == 31) warp_sums[wid] = x;
        __syncthreads();
        if (wid == 0) {
            int s = warp_sums[lane];
            #pragma unroll
            for (int o = 1; o < 32; o <<= 1) {
                int t = __shfl_up_sync(0xffffffffu, s, o);
                if (lane >= o) s += t;
            }
            warp_sums[lane] = s;
        }
        __syncthreads();
        int off = s_carry + (wid > 0 ? warp_sums[wid - 1] : 0);
        if (i < N_NODES) {
            g_rowptr[i] = off + x - v;
            g_dis[i] = rsqrtf((float)(v + 1));
        }
        int total = warp_sums[31];
        __syncthreads();
        if (tid == 0) s_carry += total;
        __syncthreads();
    }
    if (tid == 0) g_rowptr[N_NODES] = s_carry;
}

__global__ void scatter_kernel(const int* __restrict__ edge) {
    int e = blockIdx.x * blockDim.x + threadIdx.x;
    if (e < N_EDGES) {
        int s = edge[e];
        int d = edge[N_EDGES + e];
        int p = g_rowptr[d] + atomicAdd(&g_cursor[d], 1);
        g_col[p] = s;
    }
}

// ---------------- W1 pre-split: fp32 [512][156] -> bf16 hi/lo [160][512] ----
__global__ void split_w1_kernel(const float* __restrict__ W) {
    int idx = blockIdx.x * blockDim.x + threadIdx.x;
    if (idx < 160 * F_IN) {
        int n = idx >> 9;
        int k = idx & 511;
        float v = (n < HID) ? W[(size_t)k * HID + n] : 0.f;
        __nv_bfloat16 h = __float2bfloat16(v);
        g_w1t_hi[idx] = h;
        g_w1t_lo[idx] = __float2bfloat16(v - __bfloat162float(h));
    }
}

// ---------------- GEMM1 (mma.sync bf16 3-pass, cp.async B): hs = dis[m]*(x@W1) ----
// Tile M=128 x N=160. 8 warps = 4(M:32 rows) x 2(N:80 cols). K chunks of 16.
#define A_STRIDE 24
#define B_STRIDE 24
#define G1_CHUNKS (F_IN / 16)

__device__ __forceinline__ void store_a4(__nv_bfloat16* hi, __nv_bfloat16* lo,
                                         int o, float4 v) {
    __nv_bfloat16 h0 = __float2bfloat16(v.x);
    __nv_bfloat16 h1 = __float2bfloat16(v.y);
    __nv_bfloat16 h2 = __float2bfloat16(v.z);
    __nv_bfloat16 h3 = __float2bfloat16(v.w);
    float l0 = v.x - __bfloat162float(h0);
    float l1 = v.y - __bfloat162float(h1);
    float l2 = v.z - __bfloat162float(h2);
    float l3 = v.w - __bfloat162float(h3);
    *(uint2*)(hi + o) = make_uint2(pack_bf2(__bfloat162float(h0), __bfloat162float(h1)),
                                   pack_bf2(__bfloat162float(h2), __bfloat162float(h3)));
    *(uint2*)(lo + o) = make_uint2(pack_bf2(l0, l1), pack_bf2(l2, l3));
}

__global__ __launch_bounds__(256) void gemm1_mma_kernel(const float* __restrict__ X) {
    __shared__ __align__(16) __nv_bfloat16 sAhi[128 * A_STRIDE];
    __shared__ __align__(16) __nv_bfloat16 sAlo[128 * A_STRIDE];
    __shared__ __align__(16) __nv_bfloat16 sB[2][2][160 * B_STRIDE]; // [stage][hi/lo]

    int tid = threadIdx.x;
    int wid = tid >> 5;
    int lane = tid & 31;
    int warp_m = wid >> 1;     // 0..3
    int warp_n = wid & 1;      // 0..1
    int block_m = blockIdx.x * 128;

    // ldmatrix addrs
    uint32_t aHi[2], aLo[2];
    #pragma unroll
    for (int f = 0; f < 2; f++) {
        int row = warp_m * 32 + f * 16 + (lane & 15);
        uint32_t off = (uint32_t)(row * A_STRIDE * 2 + (lane >> 4) * 16);
        aHi[f] = smem_u32(sAhi) + off;
        aLo[f] = smem_u32(sAlo) + off;
    }
    int b_row_off = ((lane >> 4) & 1) * 8 + (lane & 7);
    int b_khalf   = ((lane >> 3) & 1) * 16;
    uint32_t sB_base = smem_u32(sB);
    uint32_t bOff = (uint32_t)((warp_n * 80 + b_row_off) * B_STRIDE * 2 + b_khalf);
    const uint32_t B_STAGE = 2u * 160 * B_STRIDE * 2;   // bytes per stage
    const uint32_t B_PART  = 160u * B_STRIDE * 2;       // hi -> lo

    // A LDG mapping: row = tid>>1, two float4 per chunk
    int a_row = tid >> 1;
    int a_q2 = (tid & 1) * 2;
    int a_m = block_m + a_row;
    bool a_valid = a_m < N_NODES;
    const float4* a_src = (const float4*)(X + (size_t)a_m * F_IN);
    int a_o = a_row * A_STRIDE + a_q2 * 4;

    float acc[2][10][4];
    #pragma unroll
    for (int f = 0; f < 2; f++)
        #pragma unroll
        for (int n = 0; n < 10; n++)
            #pragma unroll
            for (int c = 0; c < 4; c++) acc[f][n][c] = 0.f;

    // ---- prologue: B chunk0 -> stage0 via cp.async; A chunk0 direct
    #pragma unroll
    for (int i = 0; i < 3; i++) {
        int idx = tid + i * 256;
        if (idx < 640) {
            int part = idx >= 320;
            int r = idx - part * 320;
            int n = r >> 1, half = r & 1;
            const __nv_bfloat16* src =
                (part ? g_w1t_lo : g_w1t_hi) + (size_t)n * F_IN + half * 8;
            uint32_t dst = sB_base + (uint32_t)part * B_PART
                         + (uint32_t)((n * B_STRIDE + half * 8) * 2);
            asm volatile("cp.async.ca.shared.global [%0], [%1], 16;" :: "r"(dst), "l"(src));
        }
    }
    asm volatile("cp.async.commit_group;" ::: "memory");
    {
        float4 t0 = make_float4(0.f,0.f,0.f,0.f), t1 = t0;
        if (a_valid) { t0 = a_src[a_q2]; t1 = a_src[a_q2 + 1]; }
        store_a4(sAhi, sAlo, a_o, t0);
        store_a4(sAhi, sAlo, a_o + 4, t1);
    }
    float4 aN0 = make_float4(0.f,0.f,0.f,0.f), aN1 = aN0;
    if (a_valid) { aN0 = a_src[4 + a_q2]; aN1 = a_src[4 + a_q2 + 1]; }
    asm volatile("cp.async.wait_group 0;" ::: "memory");
    __syncthreads();

    for (int step = 0; step < G1_CHUNKS; step++) {
        int cur = step & 1;
        // ---- A fragments for current chunk
        uint32_t ah[2][4], al[2][4];
        ldm4(ah[0], aHi[0]); ldm4(ah[1], aHi[1]);
        ldm4(al[0], aLo[0]); ldm4(al[1], aLo[1]);
        __syncthreads();                       // S1: all warps done reading sA
        if (step + 1 < G1_CHUNKS) {
            // store A(step+1) from regs
            store_a4(sAhi, sAlo, a_o, aN0);
            store_a4(sAhi, sAlo, a_o + 4, aN1);
            // prefetch A(step+2)
            if (step + 2 < G1_CHUNKS) {
                int q = (step + 2) * 4;
                aN0 = make_float4(0.f,0.f,0.f,0.f); aN1 = aN0;
                if (a_valid) { aN0 = a_src[q + a_q2]; aN1 = a_src[q + a_q2 + 1]; }
            }
            // cp.async B(step+1) -> other stage
            int k0 = (step + 1) * 16;
            uint32_t stage_off = (uint32_t)(cur ^ 1) * B_STAGE;
            #pragma unroll
            for (int i = 0; i < 3; i++) {
                int idx = tid + i * 256;
                if (idx < 640) {
                    int part = idx >= 320;
                    int r = idx - part * 320;
                    int n = r >> 1, half = r & 1;
                    const __nv_bfloat16* src =
                        (part ? g_w1t_lo : g_w1t_hi) + (size_t)n * F_IN + k0 + half * 8;
                    uint32_t dst = sB_base + stage_off + (uint32_t)part * B_PART
                                 + (uint32_t)((n * B_STRIDE + half * 8) * 2);
                    asm volatile("cp.async.ca.shared.global [%0], [%1], 16;" :: "r"(dst), "l"(src));
                }
            }
            asm volatile("cp.async.commit_group;" ::: "memory");
        }
        // ---- MMA on stage cur
        uint32_t bst = sB_base + (uint32_t)cur * B_STAGE + bOff;
        #pragma unroll
        for (int p = 0; p < 5; p++) {
            uint32_t bh[4], bl[4];
            ldm4(bh, bst + (uint32_t)(p * 16 * B_STRIDE * 2));
            ldm4(bl, bst + B_PART + (uint32_t)(p * 16 * B_STRIDE * 2));
            #pragma unroll
            for (int f = 0; f < 2; f++) {
                mma16816(acc[f][2 * p],     ah[f], bh[0], bh[1]);
                mma16816(acc[f][2 * p + 1], ah[f], bh[2], bh[3]);
                mma16816(acc[f][2 * p],     ah[f], bl[0], bl[1]);
                mma16816(acc[f][2 * p + 1], ah[f], bl[2], bl[3]);
                mma16816(acc[f][2 * p],     al[f], bh[0], bh[1]);
                mma16816(acc[f][2 * p + 1], al[f], bh[2], bh[3]);
            }
        }
        if (step + 1 < G1_CHUNKS)
            asm volatile("cp.async.wait_group 0;" ::: "memory");
        __syncthreads();                       // S2: sA stores + B arrivals visible
    }

    // ---- epilogue: scale by dis[m], store
    int groupID = lane >> 2;
    int tig = lane & 3;
    #pragma unroll
    for (int f = 0; f < 2; f++) {
        int m0 = block_m + warp_m * 32 + f * 16 + groupID;
        int m1 = m0 + 8;
        bool v0 = m0 < N_NODES, v1 = m1 < N_NODES;
        float d0 = v0 ? g_dis[m0] : 0.f;
        float d1 = v1 ? g_dis[m1] : 0.f;
        float* out0 = g_hs + (size_t)m0 * HID;
        float* out1 = g_hs + (size_t)m1 * HID;
        #pragma unroll
        for (int n = 0; n < 10; n++) {
            int col = warp_n * 80 + n * 8 + tig * 2;
            if (col + 1 < HID) {
                if (v0) *(float2*)(out0 + col) = make_float2(d0 * acc[f][n][0], d0 * acc[f][n][1]);
                if (v1) *(float2*)(out1 + col) = make_float2(d1 * acc[f][n][2], d1 * acc[f][n][3]);
            }
        }
    }
}

// ---------------- agg1: a1 = relu(b1 + dis[i]*(sum_{j in N(i)} hs[j] + hs[i])) ----
__global__ __launch_bounds__(256) void agg1_kernel(const float* __restrict__ b1) {
    int warp = (blockIdx.x * blockDim.x + threadIdx.x) >> 5;
    int lane = threadIdx.x & 31;
    if (warp >= N_NODES) return;
    int i = warp;
    const float* self = g_hs + (size_t)i * HID;
    float a0 = self[lane];
    float a1v = self[lane + 32];
    float a2 = self[lane + 64];
    float a3 = self[lane + 96];
    float a4 = (lane < HID - 128) ? self[lane + 128] : 0.f;
    int s = g_rowptr[i], e = g_rowptr[i + 1];
    int p = s;
    for (; p + 1 < e; p += 2) {
        int j0 = g_col[p];
        int j1 = g_col[p + 1];
        const float* r0 = g_hs + (size_t)j0 * HID;
        const float* r1 = g_hs + (size_t)j1 * HID;
        a0 += r0[lane];      a0 += r1[lane];
        a1v += r0[lane + 32]; a1v += r1[lane + 32];
        a2 += r0[lane + 64]; a2 += r1[lane + 64];
        a3 += r0[lane + 96]; a3 += r1[lane + 96];
        if (lane < HID - 128) { a4 += r0[lane + 128]; a4 += r1[lane + 128]; }
    }
    if (p < e) {
        int j0 = g_col[p];
        const float* r0 = g_hs + (size_t)j0 * HID;
        a0 += r0[lane]; a1v += r0[lane + 32]; a2 += r0[lane + 64]; a3 += r0[lane + 96];
        if (lane < HID - 128) a4 += r0[lane + 128];
    }
    float d = g_dis[i];
    float* out = g_a1 + (size_t)i * HID;
    out[lane]       = fmaxf(d * a0 + b1[lane], 0.f);
    out[lane + 32]  = fmaxf(d * a1v + b1[lane + 32], 0.f);
    out[lane + 64]  = fmaxf(d * a2 + b1[lane + 64], 0.f);
    out[lane + 96]  = fmaxf(d * a3 + b1[lane + 96], 0.f);
    if (lane < HID - 128)
        out[lane + 128] = fmaxf(d * a4 + b1[lane + 128], 0.f);
}

// ---------------- gemm2 + scale: gs[i] = dis[i] * (a1[i] @ W2), pad col 7 = 0 ----
__global__ __launch_bounds__(256) void gemm2_kernel(const float* __restrict__ W2) {
    __shared__ float sW2[HID * N_CLS];
    for (int t = threadIdx.x; t < HID * N_CLS; t += blockDim.x) sW2[t] = W2[t];
    __syncthreads();
    int warp = (blockIdx.x * blockDim.x + threadIdx.x) >> 5;
    int lane = threadIdx.x & 31;
    if (warp >= N_NODES) return;
    int i = warp;
    const float* arow = g_a1 + (size_t)i * HID;
    float p[N_CLS];
    #pragma unroll
    for (int c = 0; c < N_CLS; c++) p[c] = 0.f;
    #pragma unroll
    for (int k = 0; k < 5; k++) {
        int f = lane + 32 * k;
        if (f < HID) {
            float a = arow[f];
            #pragma unroll
            for (int c = 0; c < N_CLS; c++) p[c] += a * sW2[f * N_CLS + c];
        }
    }
    #pragma unroll
    for (int c = 0; c < N_CLS; c++) {
        #pragma unroll
        for (int o = 16; o > 0; o >>= 1)
            p[c] += __shfl_xor_sync(0xffffffffu, p[c], o);
    }
    if (lane == 0) {
        float d = g_dis[i];
        float* out = g_gs + (size_t)i * 8;
        #pragma unroll
        for (int c = 0; c < N_CLS; c++) out[c] = d * p[c];
        out[7] = 0.f;
    }
}

// ---------------- agg2 + bias + log_softmax -> d_out ----------------
__global__ __launch_bounds__(256) void agg2_kernel(const float* __restrict__ b2,
                                                   float* __restrict__ out) {
    int t = blockIdx.x * blockDim.x + threadIdx.x;
    int i = t >> 3;
    int sl = t & 7;
    if (i >= N_NODES) return;
    float acc[8];
    #pragma unroll
    for (int c = 0; c < 8; c++) acc[c] = 0.f;
    int s = g_rowptr[i], e = g_rowptr[i + 1];
    for (int p = s + sl; p < e; p += 8) {
        int j = g_col[p];
        const float4* g = (const float4*)(g_gs + (size_t)j * 8);
        float4 u = g[0], v = g[1];
        acc[0] += u.x; acc[1] += u.y; acc[2] += u.z; acc[3] += u.w;
        acc[4] += v.x; acc[5] += v.y; acc[6] += v.z;
    }
    if (sl == 0) {
        const float4* g = (const float4*)(g_gs + (size_t)i * 8);
        float4 u = g[0], v = g[1];
        acc[0] += u.x; acc[1] += u.y; acc[2] += u.z; acc[3] += u.w;
        acc[4] += v.x; acc[5] += v.y; acc[6] += v.z;
    }
    #pragma unroll
    for (int off = 4; off > 0; off >>= 1) {
        #pragma unroll
        for (int c = 0; c < N_CLS; c++)
            acc[c] += __shfl_down_sync(0xffffffffu, acc[c], off);
    }
    if (sl == 0) {
        float d = g_dis[i];
        float v[N_CLS];
        float m = -1e30f;
        #pragma unroll
        for (int c = 0; c < N_CLS; c++) {
            v[c] = d * acc[c] + b2[c];
            m = fmaxf(m, v[c]);
        }
        float ssum = 0.f;
        #pragma unroll
        for (int c = 0; c < N_CLS; c++) ssum += __expf(v[c] - m);
        float lse = m + logf(ssum);
        float* o = out + (size_t)i * N_CLS;
        #pragma unroll
        for (int c = 0; c < N_CLS; c++) o[c] = v[c] - lse;
    }
}

// ---------------- launch ----------------
extern "C" void kernel_launch(void* const* d_in, const int* in_sizes, int n_in,
                              void* d_out, int out_size) {
    const float* x    = (const float*)d_in[0];
    const int*   edge = (const int*)d_in[1];
    const float* W1   = (const float*)d_in[2];
    const float* b1   = (const float*)d_in[3];
    const float* W2   = (const float*)d_in[4];
    const float* b2   = (const float*)d_in[5];
    float* out = (float*)d_out;

    split_w1_kernel<<<(160 * F_IN + 255) / 256, 256>>>(W1);
    zero_kernel<<<(N_NODES + 255) / 256, 256>>>();
    count_kernel<<<(N_EDGES + 255) / 256, 256>>>(edge);
    scan_kernel<<<1, 1024>>>();
    scatter_kernel<<<(N_EDGES + 255) / 256, 256>>>(edge);
    gemm1_mma_kernel<<<(N_NODES + 127) / 128, 256>>>(x);
    agg1_kernel<<<(N_NODES * 32 + 255) / 256, 256>>>(b1);
    gemm2_kernel<<<(N_NODES * 32 + 255) / 256, 256>>>(W2);
    agg2_kernel<<<(N_NODES * 8 + 255) / 256, 256>>>(b2, out);
}

// round 6
// speedup vs baseline: 2.2242x; 1.1851x over previous
#include <cuda_runtime.h>
#include <cuda_bf16.h>
#include <math.h>
#include <stdint.h>

#define N_NODES 100000
#define N_EDGES 1600000
#define F_IN 512
#define HID 156
#define N_CLS 7

#define SCAN_BLK 1024
#define SCAN_NBLK ((N_NODES + SCAN_BLK - 1) / SCAN_BLK)   // 98

// ---------------- static scratch (no allocations allowed) ----------------
__device__ float g_hs[(size_t)N_NODES * HID];   // dis[i] * (x@W1)[i]
__device__ float g_a1[(size_t)N_NODES * HID];   // relu(agg1 + b1)
__device__ float g_gs[(size_t)N_NODES * 8];     // dis[i] * (a1@W2)[i], padded to 8
__device__ int   g_deg[N_NODES];
__device__ int   g_cursor[N_NODES];
__device__ int   g_rowptr[N_NODES + 1];
__device__ int   g_col[N_EDGES];
__device__ float g_dis[N_NODES];
__device__ int   g_bsum[SCAN_NBLK];
// pre-split W1, transposed to n-major [160][512], bf16 hi/lo (rows 156..159 zero)
__device__ __nv_bfloat16 g_w1t_hi[160 * F_IN];
__device__ __nv_bfloat16 g_w1t_lo[160 * F_IN];

// ---------------- helpers ----------------
__device__ __forceinline__ uint32_t smem_u32(const void* p) {
    uint32_t a;
    asm("{ .reg .u64 t; cvta.to.shared.u64 t, %1; cvt.u32.u64 %0, t; }" : "=r"(a) : "l"(p));
    return a;
}
__device__ __forceinline__ void ldm4(uint32_t* r, uint32_t addr) {
    asm volatile("ldmatrix.sync.aligned.m8n8.x4.shared.b16 {%0,%1,%2,%3}, [%4];"
                 : "=r"(r[0]), "=r"(r[1]), "=r"(r[2]), "=r"(r[3]) : "r"(addr));
}
__device__ __forceinline__ void mma16816(float* d, const uint32_t* a,
                                         uint32_t b0, uint32_t b1) {
    asm volatile(
        "mma.sync.aligned.m16n8k16.row.col.f32.bf16.bf16.f32 "
        "{%0,%1,%2,%3}, {%4,%5,%6,%7}, {%8,%9}, {%0,%1,%2,%3};"
        : "+f"(d[0]), "+f"(d[1]), "+f"(d[2]), "+f"(d[3])
        : "r"(a[0]), "r"(a[1]), "r"(a[2]), "r"(a[3]), "r"(b0), "r"(b1));
}
__device__ __forceinline__ uint32_t pack_bf2(float a, float b) {
    __nv_bfloat162 t = __floats2bfloat162_rn(a, b);
    return *(uint32_t*)&t;
}

// ---------------- graph build ----------------
__global__ void zero_kernel() {
    int i = blockIdx.x * blockDim.x + threadIdx.x;
    if (i < N_NODES) { g_deg[i] = 0; g_cursor[i] = 0; }
}

__global__ void count_kernel(const int* __restrict__ edge) {
    int e = blockIdx.x * blockDim.x + threadIdx.x;
    if (e < N_EDGES) {
        int d = edge[N_EDGES + e];
        atomicAdd(&g_deg[d], 1);
    }
}

// ---- scan stage 1: per-block sums of g_deg
__global__ __launch_bounds__(SCAN_BLK) void bsum_kernel() {
    __shared__ int wsum[32];
    int i = blockIdx.x * SCAN_BLK + threadIdx.x;
    int lane = threadIdx.x & 31, wid = threadIdx.x >> 5;
    int v = (i < N_NODES) ? g_deg[i] : 0;
    #pragma unroll
    for (int o = 16; o > 0; o >>= 1) v += __shfl_down_sync(0xffffffffu, v, o);
    if (lane == 0) wsum[wid] = v;
    __syncthreads();
    if (wid == 0) {
        int s = (lane < SCAN_BLK / 32) ? wsum[lane] : 0;
        #pragma unroll
        for (int o = 16; o > 0; o >>= 1) s += __shfl_down_sync(0xffffffffu, s, o);
        if (lane == 0) g_bsum[blockIdx.x] = s;
    }
}

// ---- scan stage 2: exclusive scan of 98 block sums (one small block)
__global__ void bscan_kernel() {
    __shared__ int buf[128];
    int t = threadIdx.x;
    int v = (t < SCAN_NBLK) ? g_bsum[t] : 0;
    buf[t] = v;
    __syncthreads();
    #pragma unroll
    for (int o = 1; o < 128; o <<= 1) {
        int u = (t >= o) ? buf[t - o] : 0;
        __syncthreads();
        buf[t] += u;
        __syncthreads();
    }
    if (t < SCAN_NBLK) g_bsum[t] = buf[t] - v;           // exclusive
    if (t == 127) g_rowptr[N_NODES] = buf[127];           // grand total
}

// ---- scan stage 3: local exclusive scan + block offset -> rowptr, dis
__global__ __launch_bounds__(SCAN_BLK) void final_scan_kernel() {
    __shared__ int wsum[32];
    int i = blockIdx.x * SCAN_BLK + threadIdx.x;
    int lane = threadIdx.x & 31, wid = threadIdx.x >> 5;
    int v = (i < N_NODES) ? g_deg[i] : 0;
    int x = v;
    #pragma unroll
    for (int o = 1; o < 32; o <<= 1) {
        int t = __shfl_up_sync(0xffffffffu, x, o);
        if (lane >= o) x += t;
    }
    if (lane == 31) wsum[wid] = x;
    __syncthreads();
    if (wid == 0) {
        int s = (lane < SCAN_BLK / 32) ? wsum[lane] : 0;
        #pragma unroll
        for (int o = 1; o < 32; o <<= 1) {
            int t = __shfl_up_sync(0xffffffffu, s, o);
            if (lane >= o) s += t;
        }
        if (lane < SCAN_BLK / 32) wsum[lane] = s;
    }
    __syncthreads();
    if (i < N_NODES) {
        int off = g_bsum[blockIdx.x] + (wid > 0 ? wsum[wid - 1] : 0);
        g_rowptr[i] = off + x - v;                        // exclusive
        g_dis[i] = rsqrtf((float)(v + 1));
    }
}

__global__ void scatter_kernel(const int* __restrict__ edge) {
    int e = blockIdx.x * blockDim.x + threadIdx.x;
    if (e < N_EDGES) {
        int s = edge[e];
        int d = edge[N_EDGES + e];
        int p = g_rowptr[d] + atomicAdd(&g_cursor[d], 1);
        g_col[p] = s;
    }
}

// ---------------- W1 pre-split: fp32 [512][156] -> bf16 hi/lo [160][512] ----
__global__ void split_w1_kernel(const float* __restrict__ W) {
    int idx = blockIdx.x * blockDim.x + threadIdx.x;
    if (idx < 160 * F_IN) {
        int n = idx >> 9;
        int k = idx & 511;
        float v = (n < HID) ? W[(size_t)k * HID + n] : 0.f;
        __nv_bfloat16 h = __float2bfloat16(v);
        g_w1t_hi[idx] = h;
        g_w1t_lo[idx] = __float2bfloat16(v - __bfloat162float(h));
    }
}

// ---------------- GEMM1 (mma.sync bf16 3-pass, cp.async B): hs = dis[m]*(x@W1) ----
// Tile M=128 x N=160. 8 warps = 4(M:32 rows) x 2(N:80 cols). K chunks of 16.
#define A_STRIDE 24
#define B_STRIDE 24
#define G1_CHUNKS (F_IN / 16)

__device__ __forceinline__ void store_a4(__nv_bfloat16* hi, __nv_bfloat16* lo,
                                         int o, float4 v) {
    __nv_bfloat16 h0 = __float2bfloat16(v.x);
    __nv_bfloat16 h1 = __float2bfloat16(v.y);
    __nv_bfloat16 h2 = __float2bfloat16(v.z);
    __nv_bfloat16 h3 = __float2bfloat16(v.w);
    float l0 = v.x - __bfloat162float(h0);
    float l1 = v.y - __bfloat162float(h1);
    float l2 = v.z - __bfloat162float(h2);
    float l3 = v.w - __bfloat162float(h3);
    *(uint2*)(hi + o) = make_uint2(pack_bf2(__bfloat162float(h0), __bfloat162float(h1)),
                                   pack_bf2(__bfloat162float(h2), __bfloat162float(h3)));
    *(uint2*)(lo + o) = make_uint2(pack_bf2(l0, l1), pack_bf2(l2, l3));
}

__global__ __launch_bounds__(256) void gemm1_mma_kernel(const float* __restrict__ X) {
    __shared__ __align__(16) __nv_bfloat16 sAhi[128 * A_STRIDE];
    __shared__ __align__(16) __nv_bfloat16 sAlo[128 * A_STRIDE];
    __shared__ __align__(16) __nv_bfloat16 sB[2][2][160 * B_STRIDE]; // [stage][hi/lo]

    int tid = threadIdx.x;
    int wid = tid >> 5;
    int lane = tid & 31;
    int warp_m = wid >> 1;     // 0..3
    int warp_n = wid & 1;      // 0..1
    int block_m = blockIdx.x * 128;

    // ldmatrix addrs
    uint32_t aHi[2], aLo[2];
    #pragma unroll
    for (int f = 0; f < 2; f++) {
        int row = warp_m * 32 + f * 16 + (lane & 15);
        uint32_t off = (uint32_t)(row * A_STRIDE * 2 + (lane >> 4) * 16);
        aHi[f] = smem_u32(sAhi) + off;
        aLo[f] = smem_u32(sAlo) + off;
    }
    int b_row_off = ((lane >> 4) & 1) * 8 + (lane & 7);
    int b_khalf   = ((lane >> 3) & 1) * 16;
    uint32_t sB_base = smem_u32(sB);
    uint32_t bOff = (uint32_t)((warp_n * 80 + b_row_off) * B_STRIDE * 2 + b_khalf);
    const uint32_t B_STAGE = 2u * 160 * B_STRIDE * 2;   // bytes per stage
    const uint32_t B_PART  = 160u * B_STRIDE * 2;       // hi -> lo

    // A LDG mapping: row = tid>>1, two float4 per chunk
    int a_row = tid >> 1;
    int a_q2 = (tid & 1) * 2;
    int a_m = block_m + a_row;
    bool a_valid = a_m < N_NODES;
    const float4* a_src = (const float4*)(X + (size_t)a_m * F_IN);
    int a_o = a_row * A_STRIDE + a_q2 * 4;

    float acc[2][10][4];
    #pragma unroll
    for (int f = 0; f < 2; f++)
        #pragma unroll
        for (int n = 0; n < 10; n++)
            #pragma unroll
            for (int c = 0; c < 4; c++) acc[f][n][c] = 0.f;

    // ---- prologue: B chunk0 -> stage0 via cp.async; A chunk0 direct
    #pragma unroll
    for (int i = 0; i < 3; i++) {
        int idx = tid + i * 256;
        if (idx < 640) {
            int part = idx >= 320;
            int r = idx - part * 320;
            int n = r >> 1, half = r & 1;
            const __nv_bfloat16* src =
                (part ? g_w1t_lo : g_w1t_hi) + (size_t)n * F_IN + half * 8;
            uint32_t dst = sB_base + (uint32_t)part * B_PART
                         + (uint32_t)((n * B_STRIDE + half * 8) * 2);
            asm volatile("cp.async.ca.shared.global [%0], [%1], 16;" :: "r"(dst), "l"(src));
        }
    }
    asm volatile("cp.async.commit_group;" ::: "memory");
    {
        float4 t0 = make_float4(0.f,0.f,0.f,0.f), t1 = t0;
        if (a_valid) { t0 = a_src[a_q2]; t1 = a_src[a_q2 + 1]; }
        store_a4(sAhi, sAlo, a_o, t0);
        store_a4(sAhi, sAlo, a_o + 4, t1);
    }
    float4 aN0 = make_float4(0.f,0.f,0.f,0.f), aN1 = aN0;
    if (a_valid) { aN0 = a_src[4 + a_q2]; aN1 = a_src[4 + a_q2 + 1]; }
    asm volatile("cp.async.wait_group 0;" ::: "memory");
    __syncthreads();

    for (int step = 0; step < G1_CHUNKS; step++) {
        int cur = step & 1;
        // ---- A fragments for current chunk
        uint32_t ah[2][4], al[2][4];
        ldm4(ah[0], aHi[0]); ldm4(ah[1], aHi[1]);
        ldm4(al[0], aLo[0]); ldm4(al[1], aLo[1]);
        __syncthreads();                       // S1: all warps done reading sA
        if (step + 1 < G1_CHUNKS) {
            // store A(step+1) from regs
            store_a4(sAhi, sAlo, a_o, aN0);
            store_a4(sAhi, sAlo, a_o + 4, aN1);
            // prefetch A(step+2)
            if (step + 2 < G1_CHUNKS) {
                int q = (step + 2) * 4;
                aN0 = make_float4(0.f,0.f,0.f,0.f); aN1 = aN0;
                if (a_valid) { aN0 = a_src[q + a_q2]; aN1 = a_src[q + a_q2 + 1]; }
            }
            // cp.async B(step+1) -> other stage
            int k0 = (step + 1) * 16;
            uint32_t stage_off = (uint32_t)(cur ^ 1) * B_STAGE;
            #pragma unroll
            for (int i = 0; i < 3; i++) {
                int idx = tid + i * 256;
                if (idx < 640) {
                    int part = idx >= 320;
                    int r = idx - part * 320;
                    int n = r >> 1, half = r & 1;
                    const __nv_bfloat16* src =
                        (part ? g_w1t_lo : g_w1t_hi) + (size_t)n * F_IN + k0 + half * 8;
                    uint32_t dst = sB_base + stage_off + (uint32_t)part * B_PART
                                 + (uint32_t)((n * B_STRIDE + half * 8) * 2);
                    asm volatile("cp.async.ca.shared.global [%0], [%1], 16;" :: "r"(dst), "l"(src));
                }
            }
            asm volatile("cp.async.commit_group;" ::: "memory");
        }
        // ---- MMA on stage cur
        uint32_t bst = sB_base + (uint32_t)cur * B_STAGE + bOff;
        #pragma unroll
        for (int p = 0; p < 5; p++) {
            uint32_t bh[4], bl[4];
            ldm4(bh, bst + (uint32_t)(p * 16 * B_STRIDE * 2));
            ldm4(bl, bst + B_PART + (uint32_t)(p * 16 * B_STRIDE * 2));
            #pragma unroll
            for (int f = 0; f < 2; f++) {
                mma16816(acc[f][2 * p],     ah[f], bh[0], bh[1]);
                mma16816(acc[f][2 * p + 1], ah[f], bh[2], bh[3]);
                mma16816(acc[f][2 * p],     ah[f], bl[0], bl[1]);
                mma16816(acc[f][2 * p + 1], ah[f], bl[2], bl[3]);
                mma16816(acc[f][2 * p],     al[f], bh[0], bh[1]);
                mma16816(acc[f][2 * p + 1], al[f], bh[2], bh[3]);
            }
        }
        if (step + 1 < G1_CHUNKS)
            asm volatile("cp.async.wait_group 0;" ::: "memory");
        __syncthreads();                       // S2: sA stores + B arrivals visible
    }

    // ---- epilogue: scale by dis[m], store
    int groupID = lane >> 2;
    int tig = lane & 3;
    #pragma unroll
    for (int f = 0; f < 2; f++) {
        int m0 = block_m + warp_m * 32 + f * 16 + groupID;
        int m1 = m0 + 8;
        bool v0 = m0 < N_NODES, v1 = m1 < N_NODES;
        float d0 = v0 ? g_dis[m0] : 0.f;
        float d1 = v1 ? g_dis[m1] : 0.f;
        float* out0 = g_hs + (size_t)m0 * HID;
        float* out1 = g_hs + (size_t)m1 * HID;
        #pragma unroll
        for (int n = 0; n < 10; n++) {
            int col = warp_n * 80 + n * 8 + tig * 2;
            if (col + 1 < HID) {
                if (v0) *(float2*)(out0 + col) = make_float2(d0 * acc[f][n][0], d0 * acc[f][n][1]);
                if (v1) *(float2*)(out1 + col) = make_float2(d1 * acc[f][n][2], d1 * acc[f][n][3]);
            }
        }
    }
}

// ---------------- agg1: a1 = relu(b1 + dis[i]*(sum_{j in N(i)} hs[j] + hs[i])) ----
__global__ __launch_bounds__(256) void agg1_kernel(const float* __restrict__ b1) {
    int warp = (blockIdx.x * blockDim.x + threadIdx.x) >> 5;
    int lane = threadIdx.x & 31;
    if (warp >= N_NODES) return;
    int i = warp;
    const float* self = g_hs + (size_t)i * HID;
    float a0 = self[lane];
    float a1v = self[lane + 32];
    float a2 = self[lane + 64];
    float a3 = self[lane + 96];
    float a4 = (lane < HID - 128) ? self[lane + 128] : 0.f;
    int s = g_rowptr[i], e = g_rowptr[i + 1];
    int p = s;
    for (; p + 1 < e; p += 2) {
        int j0 = g_col[p];
        int j1 = g_col[p + 1];
        const float* r0 = g_hs + (size_t)j0 * HID;
        const float* r1 = g_hs + (size_t)j1 * HID;
        a0 += r0[lane];      a0 += r1[lane];
        a1v += r0[lane + 32]; a1v += r1[lane + 32];
        a2 += r0[lane + 64]; a2 += r1[lane + 64];
        a3 += r0[lane + 96]; a3 += r1[lane + 96];
        if (lane < HID - 128) { a4 += r0[lane + 128]; a4 += r1[lane + 128]; }
    }
    if (p < e) {
        int j0 = g_col[p];
        const float* r0 = g_hs + (size_t)j0 * HID;
        a0 += r0[lane]; a1v += r0[lane + 32]; a2 += r0[lane + 64]; a3 += r0[lane + 96];
        if (lane < HID - 128) a4 += r0[lane + 128];
    }
    float d = g_dis[i];
    float* out = g_a1 + (size_t)i * HID;
    out[lane]       = fmaxf(d * a0 + b1[lane], 0.f);
    out[lane + 32]  = fmaxf(d * a1v + b1[lane + 32], 0.f);
    out[lane + 64]  = fmaxf(d * a2 + b1[lane + 64], 0.f);
    out[lane + 96]  = fmaxf(d * a3 + b1[lane + 96], 0.f);
    if (lane < HID - 128)
        out[lane + 128] = fmaxf(d * a4 + b1[lane + 128], 0.f);
}

// ---------------- gemm2 + scale: gs[i] = dis[i] * (a1[i] @ W2), pad col 7 = 0 ----
__global__ __launch_bounds__(256) void gemm2_kernel(const float* __restrict__ W2) {
    __shared__ float sW2[HID * N_CLS];
    for (int t = threadIdx.x; t < HID * N_CLS; t += blockDim.x) sW2[t] = W2[t];
    __syncthreads();
    int warp = (blockIdx.x * blockDim.x + threadIdx.x) >> 5;
    int lane = threadIdx.x & 31;
    if (warp >= N_NODES) return;
    int i = warp;
    const float* arow = g_a1 + (size_t)i * HID;
    float p[N_CLS];
    #pragma unroll
    for (int c = 0; c < N_CLS; c++) p[c] = 0.f;
    #pragma unroll
    for (int k = 0; k < 5; k++) {
        int f = lane + 32 * k;
        if (f < HID) {
            float a = arow[f];
            #pragma unroll
            for (int c = 0; c < N_CLS; c++) p[c] += a * sW2[f * N_CLS + c];
        }
    }
    #pragma unroll
    for (int c = 0; c < N_CLS; c++) {
        #pragma unroll
        for (int o = 16; o > 0; o >>= 1)
            p[c] += __shfl_xor_sync(0xffffffffu, p[c], o);
    }
    if (lane == 0) {
        float d = g_dis[i];
        float* out = g_gs + (size_t)i * 8;
        #pragma unroll
        for (int c = 0; c < N_CLS; c++) out[c] = d * p[c];
        out[7] = 0.f;
    }
}

// ---------------- agg2 + bias + log_softmax -> d_out ----------------
__global__ __launch_bounds__(256) void agg2_kernel(const float* __restrict__ b2,
                                                   float* __restrict__ out) {
    int t = blockIdx.x * blockDim.x + threadIdx.x;
    int i = t >> 3;
    int sl = t & 7;
    if (i >= N_NODES) return;
    float acc[8];
    #pragma unroll
    for (int c = 0; c < 8; c++) acc[c] = 0.f;
    int s = g_rowptr[i], e = g_rowptr[i + 1];
    for (int p = s + sl; p < e; p += 8) {
        int j = g_col[p];
        const float4* g = (const float4*)(g_gs + (size_t)j * 8);
        float4 u = g[0], v = g[1];
        acc[0] += u.x; acc[1] += u.y; acc[2] += u.z; acc[3] += u.w;
        acc[4] += v.x; acc[5] += v.y; acc[6] += v.z;
    }
    if (sl == 0) {
        const float4* g = (const float4*)(g_gs + (size_t)i * 8);
        float4 u = g[0], v = g[1];
        acc[0] += u.x; acc[1] += u.y; acc[2] += u.z; acc[3] += u.w;
        acc[4] += v.x; acc[5] += v.y; acc[6] += v.z;
    }
    #pragma unroll
    for (int off = 4; off > 0; off >>= 1) {
        #pragma unroll
        for (int c = 0; c < N_CLS; c++)
            acc[c] += __shfl_down_sync(0xffffffffu, acc[c], off);
    }
    if (sl == 0) {
        float d = g_dis[i];
        float v[N_CLS];
        float m = -1e30f;
        #pragma unroll
        for (int c = 0; c < N_CLS; c++) {
            v[c] = d * acc[c] + b2[c];
            m = fmaxf(m, v[c]);
        }
        float ssum = 0.f;
        #pragma unroll
        for (int c = 0; c < N_CLS; c++) ssum += __expf(v[c] - m);
        float lse = m + logf(ssum);
        float* o = out + (size_t)i * N_CLS;
        #pragma unroll
        for (int c = 0; c < N_CLS; c++) o[c] = v[c] - lse;
    }
}

// ---------------- launch ----------------
extern "C" void kernel_launch(void* const* d_in, const int* in_sizes, int n_in,
                              void* d_out, int out_size) {
    const float* x    = (const float*)d_in[0];
    const int*   edge = (const int*)d_in[1];
    const float* W1   = (const float*)d_in[2];
    const float* b1   = (const float*)d_in[3];
    const float* W2   = (const float*)d_in[4];
    const float* b2   = (const float*)d_in[5];
    float* out = (float*)d_out;

    split_w1_kernel<<<(160 * F_IN + 255) / 256, 256>>>(W1);
    zero_kernel<<<(N_NODES + 255) / 256, 256>>>();
    count_kernel<<<(N_EDGES + 255) / 256, 256>>>(edge);
    bsum_kernel<<<SCAN_NBLK, SCAN_BLK>>>();
    bscan_kernel<<<1, 128>>>();
    final_scan_kernel<<<SCAN_NBLK, SCAN_BLK>>>();
    scatter_kernel<<<(N_EDGES + 255) / 256, 256>>>(edge);
    gemm1_mma_kernel<<<(N_NODES + 127) / 128, 256>>>(x);
    agg1_kernel<<<(N_NODES * 32 + 255) / 256, 256>>>(b1);
    gemm2_kernel<<<(N_NODES * 32 + 255) / 256, 256>>>(W2);
    agg2_kernel<<<(N_NODES * 8 + 255) / 256, 256>>>(b2, out);
}

// round 7
// speedup vs baseline: 2.4423x; 1.0981x over previous
#include <cuda_runtime.h>
#include <cuda_bf16.h>
#include <math.h>
#include <stdint.h>

#define N_NODES 100000
#define N_EDGES 1600000
#define F_IN 512
#define HID 156
#define HS_STRIDE 160            // padded row: 640B = 5 aligned 128B lines
#define N_CLS 7

#define SCAN_BLK 1024
#define SCAN_NBLK ((N_NODES + SCAN_BLK - 1) / SCAN_BLK)   // 98

// ---------------- static scratch (no allocations allowed) ----------------
__device__ float g_hs[(size_t)N_NODES * HS_STRIDE];  // dis[i]*(x@W1)[i], cols 156..159 = 0
__device__ float g_gs[(size_t)N_NODES * 8];          // dis[i]*(relu_row @ W2), padded to 8
__device__ int   g_deg[N_NODES];
__device__ int   g_cursor[N_NODES];
__device__ int   g_rowptr[N_NODES + 1];
__device__ int   g_col[N_EDGES];
__device__ float g_dis[N_NODES];
__device__ int   g_bsum[SCAN_NBLK];
// pre-split W1, transposed to n-major [160][512], bf16 hi/lo (rows 156..159 zero)
__device__ __nv_bfloat16 g_w1t_hi[160 * F_IN];
__device__ __nv_bfloat16 g_w1t_lo[160 * F_IN];

// ---------------- helpers ----------------
__device__ __forceinline__ uint32_t smem_u32(const void* p) {
    uint32_t a;
    asm("{ .reg .u64 t; cvta.to.shared.u64 t, %1; cvt.u32.u64 %0, t; }" : "=r"(a) : "l"(p));
    return a;
}
__device__ __forceinline__ void ldm4(uint32_t* r, uint32_t addr) {
    asm volatile("ldmatrix.sync.aligned.m8n8.x4.shared.b16 {%0,%1,%2,%3}, [%4];"
                 : "=r"(r[0]), "=r"(r[1]), "=r"(r[2]), "=r"(r[3]) : "r"(addr));
}
__device__ __forceinline__ void mma16816(float* d, const uint32_t* a,
                                         uint32_t b0, uint32_t b1) {
    asm volatile(
        "mma.sync.aligned.m16n8k16.row.col.f32.bf16.bf16.f32 "
        "{%0,%1,%2,%3}, {%4,%5,%6,%7}, {%8,%9}, {%0,%1,%2,%3};"
        : "+f"(d[0]), "+f"(d[1]), "+f"(d[2]), "+f"(d[3])
        : "r"(a[0]), "r"(a[1]), "r"(a[2]), "r"(a[3]), "r"(b0), "r"(b1));
}
__device__ __forceinline__ uint32_t pack_bf2(float a, float b) {
    __nv_bfloat162 t = __floats2bfloat162_rn(a, b);
    return *(uint32_t*)&t;
}

// ---------------- graph build ----------------
__global__ void zero_kernel() {
    int i = blockIdx.x * blockDim.x + threadIdx.x;
    if (i < N_NODES) { g_deg[i] = 0; g_cursor[i] = 0; }
}

__global__ void count_kernel(const int* __restrict__ edge) {
    int e = blockIdx.x * blockDim.x + threadIdx.x;
    if (e < N_EDGES) {
        int d = edge[N_EDGES + e];
        atomicAdd(&g_deg[d], 1);
    }
}

__global__ __launch_bounds__(SCAN_BLK) void bsum_kernel() {
    __shared__ int wsum[32];
    int i = blockIdx.x * SCAN_BLK + threadIdx.x;
    int lane = threadIdx.x & 31, wid = threadIdx.x >> 5;
    int v = (i < N_NODES) ? g_deg[i] : 0;
    #pragma unroll
    for (int o = 16; o > 0; o >>= 1) v += __shfl_down_sync(0xffffffffu, v, o);
    if (lane == 0) wsum[wid] = v;
    __syncthreads();
    if (wid == 0) {
        int s = (lane < SCAN_BLK / 32) ? wsum[lane] : 0;
        #pragma unroll
        for (int o = 16; o > 0; o >>= 1) s += __shfl_down_sync(0xffffffffu, s, o);
        if (lane == 0) g_bsum[blockIdx.x] = s;
    }
}

__global__ void bscan_kernel() {
    __shared__ int buf[128];
    int t = threadIdx.x;
    int v = (t < SCAN_NBLK) ? g_bsum[t] : 0;
    buf[t] = v;
    __syncthreads();
    #pragma unroll
    for (int o = 1; o < 128; o <<= 1) {
        int u = (t >= o) ? buf[t - o] : 0;
        __syncthreads();
        buf[t] += u;
        __syncthreads();
    }
    if (t < SCAN_NBLK) g_bsum[t] = buf[t] - v;           // exclusive
    if (t == 127) g_rowptr[N_NODES] = buf[127];
}

__global__ __launch_bounds__(SCAN_BLK) void final_scan_kernel() {
    __shared__ int wsum[32];
    int i = blockIdx.x * SCAN_BLK + threadIdx.x;
    int lane = threadIdx.x & 31, wid = threadIdx.x >> 5;
    int v = (i < N_NODES) ? g_deg[i] : 0;
    int x = v;
    #pragma unroll
    for (int o = 1; o < 32; o <<= 1) {
        int t = __shfl_up_sync(0xffffffffu, x, o);
        if (lane >= o) x += t;
    }
    if (lane == 31) wsum[wid] = x;
    __syncthreads();
    if (wid == 0) {
        int s = (lane < SCAN_BLK / 32) ? wsum[lane] : 0;
        #pragma unroll
        for (int o = 1; o < 32; o <<= 1) {
            int t = __shfl_up_sync(0xffffffffu, s, o);
            if (lane >= o) s += t;
        }
        if (lane < SCAN_BLK / 32) wsum[lane] = s;
    }
    __syncthreads();
    if (i < N_NODES) {
        int off = g_bsum[blockIdx.x] + (wid > 0 ? wsum[wid - 1] : 0);
        g_rowptr[i] = off + x - v;
        g_dis[i] = rsqrtf((float)(v + 1));
    }
}

__global__ void scatter_kernel(const int* __restrict__ edge) {
    int e = blockIdx.x * blockDim.x + threadIdx.x;
    if (e < N_EDGES) {
        int s = edge[e];
        int d = edge[N_EDGES + e];
        int p = g_rowptr[d] + atomicAdd(&g_cursor[d], 1);
        g_col[p] = s;
    }
}

// ---------------- W1 pre-split: fp32 [512][156] -> bf16 hi/lo [160][512] ----
__global__ void split_w1_kernel(const float* __restrict__ W) {
    int idx = blockIdx.x * blockDim.x + threadIdx.x;
    if (idx < 160 * F_IN) {
        int n = idx >> 9;
        int k = idx & 511;
        float v = (n < HID) ? W[(size_t)k * HID + n] : 0.f;
        __nv_bfloat16 h = __float2bfloat16(v);
        g_w1t_hi[idx] = h;
        g_w1t_lo[idx] = __float2bfloat16(v - __bfloat162float(h));
    }
}

// ---------------- GEMM1 (mma.sync bf16 3-pass, cp.async B): hs = dis[m]*(x@W1) ----
#define A_STRIDE 24
#define B_STRIDE 24
#define G1_CHUNKS (F_IN / 16)

__device__ __forceinline__ void store_a4(__nv_bfloat16* hi, __nv_bfloat16* lo,
                                         int o, float4 v) {
    __nv_bfloat16 h0 = __float2bfloat16(v.x);
    __nv_bfloat16 h1 = __float2bfloat16(v.y);
    __nv_bfloat16 h2 = __float2bfloat16(v.z);
    __nv_bfloat16 h3 = __float2bfloat16(v.w);
    float l0 = v.x - __bfloat162float(h0);
    float l1 = v.y - __bfloat162float(h1);
    float l2 = v.z - __bfloat162float(h2);
    float l3 = v.w - __bfloat162float(h3);
    *(uint2*)(hi + o) = make_uint2(pack_bf2(__bfloat162float(h0), __bfloat162float(h1)),
                                   pack_bf2(__bfloat162float(h2), __bfloat162float(h3)));
    *(uint2*)(lo + o) = make_uint2(pack_bf2(l0, l1), pack_bf2(l2, l3));
}

__global__ __launch_bounds__(256) void gemm1_mma_kernel(const float* __restrict__ X) {
    __shared__ __align__(16) __nv_bfloat16 sAhi[128 * A_STRIDE];
    __shared__ __align__(16) __nv_bfloat16 sAlo[128 * A_STRIDE];
    __shared__ __align__(16) __nv_bfloat16 sB[2][2][160 * B_STRIDE]; // [stage][hi/lo]

    int tid = threadIdx.x;
    int wid = tid >> 5;
    int lane = tid & 31;
    int warp_m = wid >> 1;
    int warp_n = wid & 1;
    int block_m = blockIdx.x * 128;

    uint32_t aHi[2], aLo[2];
    #pragma unroll
    for (int f = 0; f < 2; f++) {
        int row = warp_m * 32 + f * 16 + (lane & 15);
        uint32_t off = (uint32_t)(row * A_STRIDE * 2 + (lane >> 4) * 16);
        aHi[f] = smem_u32(sAhi) + off;
        aLo[f] = smem_u32(sAlo) + off;
    }
    int b_row_off = ((lane >> 4) & 1) * 8 + (lane & 7);
    int b_khalf   = ((lane >> 3) & 1) * 16;
    uint32_t sB_base = smem_u32(sB);
    uint32_t bOff = (uint32_t)((warp_n * 80 + b_row_off) * B_STRIDE * 2 + b_khalf);
    const uint32_t B_STAGE = 2u * 160 * B_STRIDE * 2;
    const uint32_t B_PART  = 160u * B_STRIDE * 2;

    int a_row = tid >> 1;
    int a_q2 = (tid & 1) * 2;
    int a_m = block_m + a_row;
    bool a_valid = a_m < N_NODES;
    const float4* a_src = (const float4*)(X + (size_t)a_m * F_IN);
    int a_o = a_row * A_STRIDE + a_q2 * 4;

    float acc[2][10][4];
    #pragma unroll
    for (int f = 0; f < 2; f++)
        #pragma unroll
        for (int n = 0; n < 10; n++)
            #pragma unroll
            for (int c = 0; c < 4; c++) acc[f][n][c] = 0.f;

    #pragma unroll
    for (int i = 0; i < 3; i++) {
        int idx = tid + i * 256;
        if (idx < 640) {
            int part = idx >= 320;
            int r = idx - part * 320;
            int n = r >> 1, half = r & 1;
            const __nv_bfloat16* src =
                (part ? g_w1t_lo : g_w1t_hi) + (size_t)n * F_IN + half * 8;
            uint32_t dst = sB_base + (uint32_t)part * B_PART
                         + (uint32_t)((n * B_STRIDE + half * 8) * 2);
            asm volatile("cp.async.ca.shared.global [%0], [%1], 16;" :: "r"(dst), "l"(src));
        }
    }
    asm volatile("cp.async.commit_group;" ::: "memory");
    {
        float4 t0 = make_float4(0.f,0.f,0.f,0.f), t1 = t0;
        if (a_valid) { t0 = a_src[a_q2]; t1 = a_src[a_q2 + 1]; }
        store_a4(sAhi, sAlo, a_o, t0);
        store_a4(sAhi, sAlo, a_o + 4, t1);
    }
    float4 aN0 = make_float4(0.f,0.f,0.f,0.f), aN1 = aN0;
    if (a_valid) { aN0 = a_src[4 + a_q2]; aN1 = a_src[4 + a_q2 + 1]; }
    asm volatile("cp.async.wait_group 0;" ::: "memory");
    __syncthreads();

    for (int step = 0; step < G1_CHUNKS; step++) {
        int cur = step & 1;
        uint32_t ah[2][4], al[2][4];
        ldm4(ah[0], aHi[0]); ldm4(ah[1], aHi[1]);
        ldm4(al[0], aLo[0]); ldm4(al[1], aLo[1]);
        __syncthreads();
        if (step + 1 < G1_CHUNKS) {
            store_a4(sAhi, sAlo, a_o, aN0);
            store_a4(sAhi, sAlo, a_o + 4, aN1);
            if (step + 2 < G1_CHUNKS) {
                int q = (step + 2) * 4;
                aN0 = make_float4(0.f,0.f,0.f,0.f); aN1 = aN0;
                if (a_valid) { aN0 = a_src[q + a_q2]; aN1 = a_src[q + a_q2 + 1]; }
            }
            int k0 = (step + 1) * 16;
            uint32_t stage_off = (uint32_t)(cur ^ 1) * B_STAGE;
            #pragma unroll
            for (int i = 0; i < 3; i++) {
                int idx = tid + i * 256;
                if (idx < 640) {
                    int part = idx >= 320;
                    int r = idx - part * 320;
                    int n = r >> 1, half = r & 1;
                    const __nv_bfloat16* src =
                        (part ? g_w1t_lo : g_w1t_hi) + (size_t)n * F_IN + k0 + half * 8;
                    uint32_t dst = sB_base + stage_off + (uint32_t)part * B_PART
                                 + (uint32_t)((n * B_STRIDE + half * 8) * 2);
                    asm volatile("cp.async.ca.shared.global [%0], [%1], 16;" :: "r"(dst), "l"(src));
                }
            }
            asm volatile("cp.async.commit_group;" ::: "memory");
        }
        uint32_t bst = sB_base + (uint32_t)cur * B_STAGE + bOff;
        #pragma unroll
        for (int p = 0; p < 5; p++) {
            uint32_t bh[4], bl[4];
            ldm4(bh, bst + (uint32_t)(p * 16 * B_STRIDE * 2));
            ldm4(bl, bst + B_PART + (uint32_t)(p * 16 * B_STRIDE * 2));
            #pragma unroll
            for (int f = 0; f < 2; f++) {
                mma16816(acc[f][2 * p],     ah[f], bh[0], bh[1]);
                mma16816(acc[f][2 * p + 1], ah[f], bh[2], bh[3]);
                mma16816(acc[f][2 * p],     ah[f], bl[0], bl[1]);
                mma16816(acc[f][2 * p + 1], ah[f], bl[2], bl[3]);
                mma16816(acc[f][2 * p],     al[f], bh[0], bh[1]);
                mma16816(acc[f][2 * p + 1], al[f], bh[2], bh[3]);
            }
        }
        if (step + 1 < G1_CHUNKS)
            asm volatile("cp.async.wait_group 0;" ::: "memory");
        __syncthreads();
    }

    // ---- epilogue: scale by dis[m], store full padded rows (pad cols = 0)
    int groupID = lane >> 2;
    int tig = lane & 3;
    #pragma unroll
    for (int f = 0; f < 2; f++) {
        int m0 = block_m + warp_m * 32 + f * 16 + groupID;
        int m1 = m0 + 8;
        bool v0 = m0 < N_NODES, v1 = m1 < N_NODES;
        float d0 = v0 ? g_dis[m0] : 0.f;
        float d1 = v1 ? g_dis[m1] : 0.f;
        float* out0 = g_hs + (size_t)m0 * HS_STRIDE;
        float* out1 = g_hs + (size_t)m1 * HS_STRIDE;
        #pragma unroll
        for (int n = 0; n < 10; n++) {
            int col = warp_n * 80 + n * 8 + tig * 2;
            if (v0) *(float2*)(out0 + col) = make_float2(d0 * acc[f][n][0], d0 * acc[f][n][1]);
            if (v1) *(float2*)(out1 + col) = make_float2(d1 * acc[f][n][2], d1 * acc[f][n][3]);
        }
    }
}

// ---------------- fused agg1 + gemm2:
// row = relu(b1 + dis[i]*(sum_{j in N(i)} hs[j] + hs[i]));  gs[i] = dis[i]*(row @ W2)
__global__ __launch_bounds__(256) void agg1_gemm2_kernel(const float* __restrict__ b1,
                                                         const float* __restrict__ W2) {
    __shared__ float sW2[HID * N_CLS];
    for (int t = threadIdx.x; t < HID * N_CLS; t += blockDim.x) sW2[t] = W2[t];
    __syncthreads();

    int warp = (blockIdx.x * blockDim.x + threadIdx.x) >> 5;
    int lane = threadIdx.x & 31;
    if (warp >= N_NODES) return;
    int i = warp;
    const float* self = g_hs + (size_t)i * HS_STRIDE;
    float a0 = self[lane];
    float a1v = self[lane + 32];
    float a2 = self[lane + 64];
    float a3 = self[lane + 96];
    float a4 = self[lane + 128];          // pad cols are exact zeros
    int s = g_rowptr[i], e = g_rowptr[i + 1];
    int p = s;
    for (; p + 1 < e; p += 2) {
        int j0 = g_col[p];
        int j1 = g_col[p + 1];
        const float* r0 = g_hs + (size_t)j0 * HS_STRIDE;
        const float* r1 = g_hs + (size_t)j1 * HS_STRIDE;
        a0 += r0[lane];       a0 += r1[lane];
        a1v += r0[lane + 32]; a1v += r1[lane + 32];
        a2 += r0[lane + 64];  a2 += r1[lane + 64];
        a3 += r0[lane + 96];  a3 += r1[lane + 96];
        a4 += r0[lane + 128]; a4 += r1[lane + 128];
    }
    if (p < e) {
        int j0 = g_col[p];
        const float* r0 = g_hs + (size_t)j0 * HS_STRIDE;
        a0 += r0[lane]; a1v += r0[lane + 32]; a2 += r0[lane + 64];
        a3 += r0[lane + 96]; a4 += r0[lane + 128];
    }
    float d = g_dis[i];
    // relu(b1 + d*sum) for the 5 features this lane owns
    float v0 = fmaxf(d * a0 + b1[lane], 0.f);
    float v1 = fmaxf(d * a1v + b1[lane + 32], 0.f);
    float v2 = fmaxf(d * a2 + b1[lane + 64], 0.f);
    float v3 = fmaxf(d * a3 + b1[lane + 96], 0.f);
    float v4 = (lane < HID - 128) ? fmaxf(d * a4 + b1[lane + 128], 0.f) : 0.f;

    // row @ W2 (W2 rows distributed over lanes), warp-reduce
    float pr[N_CLS];
    #pragma unroll
    for (int c = 0; c < N_CLS; c++) {
        float t = v0 * sW2[lane * N_CLS + c]
                + v1 * sW2[(lane + 32) * N_CLS + c]
                + v2 * sW2[(lane + 64) * N_CLS + c]
                + v3 * sW2[(lane + 96) * N_CLS + c];
        if (lane < HID - 128) t += v4 * sW2[(lane + 128) * N_CLS + c];
        pr[c] = t;
    }
    #pragma unroll
    for (int c = 0; c < N_CLS; c++) {
        #pragma unroll
        for (int o = 16; o > 0; o >>= 1)
            pr[c] += __shfl_xor_sync(0xffffffffu, pr[c], o);
    }
    if (lane == 0) {
        float* out = g_gs + (size_t)i * 8;
        #pragma unroll
        for (int c = 0; c < N_CLS; c++) out[c] = d * pr[c];
        out[7] = 0.f;
    }
}

// ---------------- agg2 + bias + log_softmax -> d_out ----------------
__global__ __launch_bounds__(256) void agg2_kernel(const float* __restrict__ b2,
                                                   float* __restrict__ out) {
    int t = blockIdx.x * blockDim.x + threadIdx.x;
    int i = t >> 3;
    int sl = t & 7;
    if (i >= N_NODES) return;
    float acc[8];
    #pragma unroll
    for (int c = 0; c < 8; c++) acc[c] = 0.f;
    int s = g_rowptr[i], e = g_rowptr[i + 1];
    for (int p = s + sl; p < e; p += 8) {
        int j = g_col[p];
        const float4* g = (const float4*)(g_gs + (size_t)j * 8);
        float4 u = g[0], v = g[1];
        acc[0] += u.x; acc[1] += u.y; acc[2] += u.z; acc[3] += u.w;
        acc[4] += v.x; acc[5] += v.y; acc[6] += v.z;
    }
    if (sl == 0) {
        const float4* g = (const float4*)(g_gs + (size_t)i * 8);
        float4 u = g[0], v = g[1];
        acc[0] += u.x; acc[1] += u.y; acc[2] += u.z; acc[3] += u.w;
        acc[4] += v.x; acc[5] += v.y; acc[6] += v.z;
    }
    #pragma unroll
    for (int off = 4; off > 0; off >>= 1) {
        #pragma unroll
        for (int c = 0; c < N_CLS; c++)
            acc[c] += __shfl_down_sync(0xffffffffu, acc[c], off);
    }
    if (sl == 0) {
        float d = g_dis[i];
        float v[N_CLS];
        float m = -1e30f;
        #pragma unroll
        for (int c = 0; c < N_CLS; c++) {
            v[c] = d * acc[c] + b2[c];
            m = fmaxf(m, v[c]);
        }
        float ssum = 0.f;
        #pragma unroll
        for (int c = 0; c < N_CLS; c++) ssum += __expf(v[c] - m);
        float lse = m + logf(ssum);
        float* o = out + (size_t)i * N_CLS;
        #pragma unroll
        for (int c = 0; c < N_CLS; c++) o[c] = v[c] - lse;
    }
}

// ---------------- launch ----------------
extern "C" void kernel_launch(void* const* d_in, const int* in_sizes, int n_in,
                              void* d_out, int out_size) {
    const float* x    = (const float*)d_in[0];
    const int*   edge = (const int*)d_in[1];
    const float* W1   = (const float*)d_in[2];
    const float* b1   = (const float*)d_in[3];
    const float* W2   = (const float*)d_in[4];
    const float* b2   = (const float*)d_in[5];
    float* out = (float*)d_out;

    split_w1_kernel<<<(160 * F_IN + 255) / 256, 256>>>(W1);
    zero_kernel<<<(N_NODES + 255) / 256, 256>>>();
    count_kernel<<<(N_EDGES + 255) / 256, 256>>>(edge);
    bsum_kernel<<<SCAN_NBLK, SCAN_BLK>>>();
    bscan_kernel<<<1, 128>>>();
    final_scan_kernel<<<SCAN_NBLK, SCAN_BLK>>>();
    scatter_kernel<<<(N_EDGES + 255) / 256, 256>>>(edge);
    gemm1_mma_kernel<<<(N_NODES + 127) / 128, 256>>>(x);
    agg1_gemm2_kernel<<<(N_NODES * 32 + 255) / 256, 256>>>(b1, W2);
    agg2_kernel<<<(N_NODES * 8 + 255) / 256, 256>>>(b2, out);
}